// round 5
// baseline (speedup 1.0000x reference)
#include <cuda_runtime.h>
#include <cstdint>

#define NDIM 16384
#define BDIM 512
#define NNZ  131072
#define B4   (BDIM/4)   // 128 float4 per column

// ---------------- device scratch (static allocation; no cudaMalloc) -------------
__device__ __align__(16) float g_h0[(size_t)NDIM * BDIM];   // h ping  (N, B) layout
__device__ __align__(16) float g_h1[(size_t)NDIM * BDIM];   // h pong
__device__ __align__(16) float g_c [(size_t)NDIM * BDIM];   // cell state (N, B)

__device__ int   g_colcnt[NDIM];
__device__ int   g_colstart[NDIM + 1];
__device__ int   g_cur[NDIM];
__device__ int   g_cscrow[NNZ];
__device__ float g_cscval[NNZ];
__device__ int   g_csceid[NNZ];
__device__ int   g_idx_nonzero_odd;   // >0 -> indices are int32; ==0 -> int64

// ---------------- dtype detection + init ----------------------------------------
__global__ void k_zero_cnt() {
    int i = blockIdx.x * blockDim.x + threadIdx.x;
    if (i == 0) g_idx_nonzero_odd = 0;
    for (; i < NDIM; i += gridDim.x * blockDim.x)
        g_colcnt[i] = 0;
}

// Inspect 32-bit words of the index buffer. int64 data (values < 2^31) -> all odd
// words are zero hi-halves. int32 data -> odd words are column ids, not all zero.
__global__ void k_detect(const int* __restrict__ w) {
    int i = blockIdx.x * blockDim.x + threadIdx.x;   // odd-word index
    if (i < NNZ) {
        if (w[2 * i + 1] != 0) atomicOr(&g_idx_nonzero_odd, 1);
    }
}

__device__ __forceinline__ void load_rc(const void* idx, int e, int& row, int& col) {
    if (g_idx_nonzero_odd) {               // int32 pairs
        const int* p = (const int*)idx;
        row = p[2 * e + 0];
        col = p[2 * e + 1];
    } else {                               // int64 pairs
        const long long* p = (const long long*)idx;
        row = (int)p[2 * e + 0];
        col = (int)p[2 * e + 1];
    }
    row &= (NDIM - 1);
    col &= (NDIM - 1);
}

__global__ void k_hist(const void* __restrict__ idx) {
    int e = blockIdx.x * blockDim.x + threadIdx.x;
    if (e < NNZ) {
        int row, col;
        load_rc(idx, e, row, col);
        atomicAdd(&g_colcnt[col], 1);
    }
}

// single block, 256 threads; each thread owns 64 consecutive bins
__global__ void k_scan() {
    __shared__ int part[256];
    int t = threadIdx.x;
    int base = t * 64;
    int s = 0;
    #pragma unroll
    for (int k = 0; k < 64; k++) s += g_colcnt[base + k];
    part[t] = s;
    __syncthreads();
    for (int off = 1; off < 256; off <<= 1) {
        int add = (t >= off) ? part[t - off] : 0;
        __syncthreads();
        part[t] += add;
        __syncthreads();
    }
    int run = (t == 0) ? 0 : part[t - 1];
    #pragma unroll
    for (int k = 0; k < 64; k++) {
        g_colstart[base + k] = run;
        g_cur[base + k] = run;
        run += g_colcnt[base + k];
    }
    if (t == 255) g_colstart[NDIM] = run;   // == NNZ
}

__global__ void k_scatter(const void* __restrict__ idx,
                          const float* __restrict__ vals) {
    int e = blockIdx.x * blockDim.x + threadIdx.x;
    if (e < NNZ) {
        int row, col;
        load_rc(idx, e, row, col);
        int pos = atomicAdd(&g_cur[col], 1);
        g_cscrow[pos] = row;
        g_cscval[pos] = vals[e];
        g_csceid[pos] = e;
    }
}

// deterministic order: insertion-sort each segment by original entry id
__global__ void k_segsort() {
    int col = blockIdx.x * blockDim.x + threadIdx.x;
    if (col >= NDIM) return;
    int s = g_colstart[col], e = g_colstart[col + 1];
    for (int a = s + 1; a < e; a++) {
        int   keid = g_csceid[a];
        int   kr   = g_cscrow[a];
        float kv   = g_cscval[a];
        int b = a - 1;
        while (b >= s && g_csceid[b] > keid) {
            g_csceid[b + 1] = g_csceid[b];
            g_cscrow[b + 1] = g_cscrow[b];
            g_cscval[b + 1] = g_cscval[b];
            b--;
        }
        g_csceid[b + 1] = keid;
        g_cscrow[b + 1] = kr;
        g_cscval[b + 1] = kv;
    }
}

// ---------------- transpose in: x (B,N) -> g_h0 (N,B); zero g_c -----------------
__global__ void k_transpose_in(const float* __restrict__ x) {
    __shared__ float tile[32][33];
    int nBase = blockIdx.x * 32;
    int bBase = blockIdx.y * 32;
    int tx = threadIdx.x, ty = threadIdx.y;
    #pragma unroll
    for (int i = ty; i < 32; i += 8)
        tile[i][tx] = x[(size_t)(bBase + i) * NDIM + nBase + tx];
    __syncthreads();
    #pragma unroll
    for (int i = ty; i < 32; i += 8) {
        size_t o = (size_t)(nBase + i) * BDIM + bBase + tx;
        g_h0[o] = tile[tx][i];
        g_c[o]  = 0.0f;
    }
}

// ---------------- fused SpMM + LSTM gate iteration ------------------------------
__device__ __forceinline__ float lstm_elem(float z, float& c,
                                           float ebi, float ebf, float ebo, float ebg2) {
    float ez = __expf(-z);
    float i = __fdividef(1.0f, 1.0f + ez * ebi);
    float f = __fdividef(1.0f, 1.0f + ez * ebf);
    float o = __fdividef(1.0f, 1.0f + ez * ebo);
    float w = ez * ez * ebg2;                         // e^{-2(z+b_g)}
    float g = __fdividef(2.0f, 1.0f + w) - 1.0f;      // tanh(z+b_g)
    c = f * c + i * g;
    float ec = __expf(-2.0f * c);
    float th = __fdividef(1.0f - ec, 1.0f + ec);      // tanh(c)
    return o * th;
}

// flip==0: read g_h0, write g_h1.  flip==1: read g_h1, write g_h0.
// Device symbols are resolved IN DEVICE CODE (host-side symbol addresses are
// invalid; on GB300/ATS they silently alias host memory -- the R2-R4 bug).
__global__ void __launch_bounds__(128)
k_iter(int flip,
       const float* __restrict__ bi_, const float* __restrict__ bf_,
       const float* __restrict__ bo_, const float* __restrict__ bg_) {
    const float* hsrc = flip ? g_h1 : g_h0;
    float*       hdst = flip ? g_h0 : g_h1;

    int col = blockIdx.x;
    int t   = threadIdx.x;                 // 0..127, owns 4 batch elems via float4
    int s = g_colstart[col], e = g_colstart[col + 1];

    const float4* hp = (const float4*)hsrc;
    float4 acc = make_float4(0.f, 0.f, 0.f, 0.f);
    for (int j = s; j < e; j++) {
        int   r = g_cscrow[j];
        float v = g_cscval[j];
        float4 hv = hp[(size_t)r * B4 + t];
        acc.x = fmaf(v, hv.x, acc.x);
        acc.y = fmaf(v, hv.y, acc.y);
        acc.z = fmaf(v, hv.z, acc.z);
        acc.w = fmaf(v, hv.w, acc.w);
    }

    float ebi  = __expf(-bi_[col]);
    float ebf  = __expf(-bf_[col]);
    float ebo  = __expf(-bo_[col]);
    float ebg2 = __expf(-2.0f * bg_[col]);

    size_t co = (size_t)col * B4 + t;
    float4* cp = (float4*)g_c;
    float4  cv = cp[co];

    float4 hout;
    hout.x = lstm_elem(acc.x, cv.x, ebi, ebf, ebo, ebg2);
    hout.y = lstm_elem(acc.y, cv.y, ebi, ebf, ebo, ebg2);
    hout.z = lstm_elem(acc.z, cv.z, ebi, ebf, ebo, ebg2);
    hout.w = lstm_elem(acc.w, cv.w, ebi, ebf, ebo, ebg2);

    cp[co] = cv;
    ((float4*)hdst)[co] = hout;
}

// ---------------- transpose out: g_h0 (N,B) -> out (B,N) ------------------------
__global__ void k_transpose_out(float* __restrict__ out) {
    __shared__ float tile[32][33];
    int nBase = blockIdx.x * 32;
    int bBase = blockIdx.y * 32;
    int tx = threadIdx.x, ty = threadIdx.y;
    #pragma unroll
    for (int i = ty; i < 32; i += 8)
        tile[i][tx] = g_h0[(size_t)(nBase + i) * BDIM + bBase + tx];
    __syncthreads();
    #pragma unroll
    for (int i = ty; i < 32; i += 8)
        out[(size_t)(bBase + i) * NDIM + nBase + tx] = tile[tx][i];
}

// ---------------- launch ---------------------------------------------------------
extern "C" void kernel_launch(void* const* d_in, const int* in_sizes, int n_in,
                              void* d_out, int out_size) {
    // Size-based input identification (robust to metadata ordering):
    //   x: 8388608 elems, kernel: 131072, biases: 16384 (x4, relative order kept),
    //   sparse_indices: the remaining buffer.
    const float* x    = nullptr;
    const float* vals = nullptr;
    const float* bias[4] = {nullptr, nullptr, nullptr, nullptr};
    const void*  idx  = nullptr;
    int nbias = 0;
    for (int i = 0; i < n_in; i++) {
        int sz = in_sizes[i];
        if (sz == NDIM * BDIM)       x = (const float*)d_in[i];
        else if (sz == NNZ)          vals = (const float*)d_in[i];
        else if (sz == NDIM)         { if (nbias < 4) bias[nbias++] = (const float*)d_in[i]; }
        else                         idx = d_in[i];
    }
    const float* b_i = bias[0];
    const float* b_f = bias[1];
    const float* b_o = bias[2];
    const float* b_g = bias[3];
    float* out = (float*)d_out;
    (void)out_size;

    // build CSC (deterministic via segment sort on entry id)
    k_zero_cnt<<<64, 256>>>();
    k_detect<<<(NNZ + 255) / 256, 256>>>((const int*)idx);
    k_hist<<<(NNZ + 255) / 256, 256>>>(idx);
    k_scan<<<1, 256>>>();
    k_scatter<<<(NNZ + 255) / 256, 256>>>(idx, vals);
    k_segsort<<<(NDIM + 255) / 256, 256>>>();

    // state init: h = x^T, c = 0
    dim3 tb(32, 8);
    dim3 tg(NDIM / 32, BDIM / 32);
    k_transpose_in<<<tg, tb>>>(x);

    // 4 fused iterations with h ping-pong: h0->h1->h0->h1->h0
    k_iter<<<NDIM, 128>>>(0, b_i, b_f, b_o, b_g);
    k_iter<<<NDIM, 128>>>(1, b_i, b_f, b_o, b_g);
    k_iter<<<NDIM, 128>>>(0, b_i, b_f, b_o, b_g);
    k_iter<<<NDIM, 128>>>(1, b_i, b_f, b_o, b_g);

    // out (B,N) = transpose(g_h0)
    k_transpose_out<<<tg, tb>>>(out);
}

// round 7
// speedup vs baseline: 1.1681x; 1.1681x over previous
#include <cuda_runtime.h>
#include <cstdint>

#define NDIM 16384
#define BDIM 512
#define NNZ  131072
#define B4   (BDIM/4)   // 128 float4 per column

// ---------------- device scratch (static allocation; no cudaMalloc) -------------
__device__ __align__(16) float g_h0[(size_t)NDIM * BDIM];   // h ping  (N, B) layout
__device__ __align__(16) float g_h1[(size_t)NDIM * BDIM];   // h pong
__device__ __align__(16) float g_c [(size_t)NDIM * BDIM];   // cell state (N, B)

__device__ int                g_colcnt[NDIM];
__device__ int                g_colstart[NDIM + 1];
__device__ int                g_cur[NDIM];
__device__ unsigned long long g_pack[NNZ];      // [62:46]=eid [45:32]=row [31:0]=val bits
__device__ int                g_idx_nonzero_odd = 0;   // monotonic 0->1; pure fn of input

// ---------------- init: zero counters + index-dtype detection (fused) ------------
// int64 data (values < 2^31) -> all odd 32-bit words are zero hi-halves.
// int32 data -> odd words are column ids, not all zero.
__global__ void k_init(const int* __restrict__ w) {
    int i = blockIdx.x * blockDim.x + threadIdx.x;
    if (i < NDIM) g_colcnt[i] = 0;
    if (i < NNZ && w[2 * i + 1] != 0) atomicOr(&g_idx_nonzero_odd, 1);
}

__device__ __forceinline__ void load_rc(const void* idx, int e, int& row, int& col) {
    if (g_idx_nonzero_odd) {               // int32 pairs
        const int* p = (const int*)idx;
        row = p[2 * e + 0];
        col = p[2 * e + 1];
    } else {                               // int64 pairs
        const long long* p = (const long long*)idx;
        row = (int)p[2 * e + 0];
        col = (int)p[2 * e + 1];
    }
    row &= (NDIM - 1);
    col &= (NDIM - 1);
}

__global__ void k_hist(const void* __restrict__ idx) {
    int e = blockIdx.x * blockDim.x + threadIdx.x;
    if (e < NNZ) {
        int row, col;
        load_rc(idx, e, row, col);
        atomicAdd(&g_colcnt[col], 1);
    }
}

// 1024 threads, 1 block: int4 loads, shfl warp scan + block scan over warp sums
__global__ void __launch_bounds__(1024) k_scan() {
    __shared__ int ws[32];
    int t = threadIdx.x;                 // 0..1023, owns 16 consecutive bins
    const int4* cc = (const int4*)g_colcnt;
    int4 a0 = cc[t * 4 + 0], a1 = cc[t * 4 + 1], a2 = cc[t * 4 + 2], a3 = cc[t * 4 + 3];
    int v[16] = {a0.x, a0.y, a0.z, a0.w, a1.x, a1.y, a1.z, a1.w,
                 a2.x, a2.y, a2.z, a2.w, a3.x, a3.y, a3.z, a3.w};
    int tot = 0;
    #pragma unroll
    for (int k = 0; k < 16; k++) tot += v[k];

    int lane = t & 31, w = t >> 5;
    int sc = tot;                        // warp-inclusive scan of per-thread totals
    #pragma unroll
    for (int off = 1; off < 32; off <<= 1) {
        int n = __shfl_up_sync(0xffffffffu, sc, off);
        if (lane >= off) sc += n;
    }
    if (lane == 31) ws[w] = sc;
    __syncthreads();
    if (w == 0) {
        int x = ws[lane];
        #pragma unroll
        for (int off = 1; off < 32; off <<= 1) {
            int n = __shfl_up_sync(0xffffffffu, x, off);
            if (lane >= off) x += n;
        }
        ws[lane] = x;
    }
    __syncthreads();
    int base = (w ? ws[w - 1] : 0) + (sc - tot);   // exclusive offset for this thread
    #pragma unroll
    for (int k = 0; k < 16; k++) {
        g_colstart[t * 16 + k] = base;
        g_cur[t * 16 + k] = base;
        base += v[k];
    }
    if (t == 1023) g_colstart[NDIM] = base;   // == NNZ
}

__global__ void k_scatter(const void* __restrict__ idx,
                          const float* __restrict__ vals) {
    int e = blockIdx.x * blockDim.x + threadIdx.x;
    if (e < NNZ) {
        int row, col;
        load_rc(idx, e, row, col);
        int pos = atomicAdd(&g_cur[col], 1);
        unsigned long long p = ((unsigned long long)e << 46)
                             | ((unsigned long long)(unsigned)row << 32)
                             | (unsigned)__float_as_int(vals[e]);
        g_pack[pos] = p;
    }
}

// deterministic order: sort each segment by packed key (eid in top bits)
__global__ void k_segsort() {
    int col = blockIdx.x * blockDim.x + threadIdx.x;
    if (col >= NDIM) return;
    int s = g_colstart[col], e = g_colstart[col + 1], n = e - s;
    if (n <= 1) return;
    if (n <= 32) {
        unsigned long long buf[32];
        for (int k = 0; k < n; k++) buf[k] = g_pack[s + k];
        for (int a = 1; a < n; a++) {
            unsigned long long key = buf[a];
            int b = a - 1;
            while (b >= 0 && buf[b] > key) { buf[b + 1] = buf[b]; b--; }
            buf[b + 1] = key;
        }
        for (int k = 0; k < n; k++) g_pack[s + k] = buf[k];
    } else {  // rare fallback
        for (int a = s + 1; a < e; a++) {
            unsigned long long key = g_pack[a];
            int b = a - 1;
            while (b >= s && g_pack[b] > key) { g_pack[b + 1] = g_pack[b]; b--; }
            g_pack[b + 1] = key;
        }
    }
}

// ---------------- transpose in: x (B,N) -> g_h0 (N,B) ---------------------------
__global__ void k_transpose_in(const float* __restrict__ x) {
    __shared__ float tile[32][33];
    int nBase = blockIdx.x * 32;
    int bBase = blockIdx.y * 32;
    int tx = threadIdx.x, ty = threadIdx.y;
    #pragma unroll
    for (int i = ty; i < 32; i += 8)
        tile[i][tx] = x[(size_t)(bBase + i) * NDIM + nBase + tx];
    __syncthreads();
    #pragma unroll
    for (int i = ty; i < 32; i += 8)
        g_h0[(size_t)(nBase + i) * BDIM + bBase + tx] = tile[tx][i];
}

// ---------------- fused SpMM + LSTM gate iteration ------------------------------
__device__ __forceinline__ float lstm_elem(float z, float& c,
                                           float ebi, float ebf, float ebo, float ebg2) {
    float ez = __expf(-z);
    float i = __fdividef(1.0f, 1.0f + ez * ebi);
    float f = __fdividef(1.0f, 1.0f + ez * ebf);
    float o = __fdividef(1.0f, 1.0f + ez * ebo);
    float w = ez * ez * ebg2;                         // e^{-2(z+b_g)}
    float g = __fdividef(2.0f, 1.0f + w) - 1.0f;      // tanh(z+b_g)
    c = f * c + i * g;
    float ec = __expf(-2.0f * c);
    float th = __fdividef(1.0f - ec, 1.0f + ec);      // tanh(c)
    return o * th;
}

// flip==0: read g_h0 write g_h1; flip==1: read g_h1 write g_h0.
// first: c starts at 0 (skip load). last: nobody reads c (skip store).
__global__ void __launch_bounds__(128)
k_iter(int flip, int first, int last,
       const float* __restrict__ bi_, const float* __restrict__ bf_,
       const float* __restrict__ bo_, const float* __restrict__ bg_) {
    const float4* hp = (const float4*)(flip ? g_h1 : g_h0);
    float4*       hd = (float4*)(flip ? g_h0 : g_h1);

    int col = blockIdx.x;
    int t   = threadIdx.x;                 // 0..127, owns 4 batch elems via float4
    int s = g_colstart[col], e = g_colstart[col + 1];

    float4 acc = make_float4(0.f, 0.f, 0.f, 0.f);
    int j = s;
    unsigned long long pf = (j < e) ? g_pack[j] : 0ull;
    while (j < e) {
        unsigned long long p = pf;
        if (j + 1 < e) pf = g_pack[j + 1];
        int   r = (int)((p >> 32) & 0x3FFFu);
        float v = __int_as_float((int)(unsigned)p);
        float4 hv = hp[(size_t)r * B4 + t];
        acc.x = fmaf(v, hv.x, acc.x);
        acc.y = fmaf(v, hv.y, acc.y);
        acc.z = fmaf(v, hv.z, acc.z);
        acc.w = fmaf(v, hv.w, acc.w);
        j++;
    }

    float ebi  = __expf(-bi_[col]);
    float ebf  = __expf(-bf_[col]);
    float ebo  = __expf(-bo_[col]);
    float ebg2 = __expf(-2.0f * bg_[col]);

    size_t co = (size_t)col * B4 + t;
    float4* cp = (float4*)g_c;
    float4  cv = first ? make_float4(0.f, 0.f, 0.f, 0.f) : cp[co];

    float4 hout;
    hout.x = lstm_elem(acc.x, cv.x, ebi, ebf, ebo, ebg2);
    hout.y = lstm_elem(acc.y, cv.y, ebi, ebf, ebo, ebg2);
    hout.z = lstm_elem(acc.z, cv.z, ebi, ebf, ebo, ebg2);
    hout.w = lstm_elem(acc.w, cv.w, ebi, ebf, ebo, ebg2);

    if (!last) cp[co] = cv;
    hd[co] = hout;
}

// ---------------- transpose out: g_h0 (N,B) -> out (B,N) ------------------------
__global__ void k_transpose_out(float* __restrict__ out) {
    __shared__ float tile[32][33];
    int nBase = blockIdx.x * 32;
    int bBase = blockIdx.y * 32;
    int tx = threadIdx.x, ty = threadIdx.y;
    #pragma unroll
    for (int i = ty; i < 32; i += 8)
        tile[i][tx] = g_h0[(size_t)(nBase + i) * BDIM + bBase + tx];
    __syncthreads();
    #pragma unroll
    for (int i = ty; i < 32; i += 8)
        out[(size_t)(bBase + i) * NDIM + nBase + tx] = tile[tx][i];
}

// ---------------- launch ---------------------------------------------------------
extern "C" void kernel_launch(void* const* d_in, const int* in_sizes, int n_in,
                              void* d_out, int out_size) {
    // Size-based input identification (robust to metadata ordering):
    //   x: 8388608 elems, kernel: 131072, biases: 16384 (x4, relative order kept),
    //   sparse_indices: the remaining buffer.
    const float* x    = nullptr;
    const float* vals = nullptr;
    const float* bias[4] = {nullptr, nullptr, nullptr, nullptr};
    const void*  idx  = nullptr;
    int nbias = 0;
    for (int i = 0; i < n_in; i++) {
        int sz = in_sizes[i];
        if (sz == NDIM * BDIM)       x = (const float*)d_in[i];
        else if (sz == NNZ)          vals = (const float*)d_in[i];
        else if (sz == NDIM)         { if (nbias < 4) bias[nbias++] = (const float*)d_in[i]; }
        else                         idx = d_in[i];
    }
    const float* b_i = bias[0];
    const float* b_f = bias[1];
    const float* b_o = bias[2];
    const float* b_g = bias[3];
    float* out = (float*)d_out;
    (void)out_size;

    // build CSC (deterministic via per-segment sort on packed entry id)
    k_init   <<<(NNZ + 255) / 256, 256>>>((const int*)idx);
    k_hist   <<<(NNZ + 255) / 256, 256>>>(idx);
    k_scan   <<<1, 1024>>>();
    k_scatter<<<(NNZ + 255) / 256, 256>>>(idx, vals);
    k_segsort<<<(NDIM + 255) / 256, 256>>>();

    // state init: h = x^T (c handled by `first` flag)
    dim3 tb(32, 8);
    dim3 tg(NDIM / 32, BDIM / 32);
    k_transpose_in<<<tg, tb>>>(x);

    // 4 fused iterations with h ping-pong: h0->h1->h0->h1->h0
    k_iter<<<NDIM, 128>>>(0, 1, 0, b_i, b_f, b_o, b_g);
    k_iter<<<NDIM, 128>>>(1, 0, 0, b_i, b_f, b_o, b_g);
    k_iter<<<NDIM, 128>>>(0, 0, 0, b_i, b_f, b_o, b_g);
    k_iter<<<NDIM, 128>>>(1, 0, 1, b_i, b_f, b_o, b_g);

    // out (B,N) = transpose(g_h0)
    k_transpose_out<<<tg, tb>>>(out);
}

// round 8
// speedup vs baseline: 1.2613x; 1.0798x over previous
#include <cuda_runtime.h>
#include <cuda_fp16.h>
#include <cstdint>

#define NDIM 16384
#define BDIM 512
#define NNZ  131072
#define B4   (BDIM/4)   // 128 float4 per column (fp32 view)
#define BH4  (BDIM/4)   // 128 uint2 per column (half4 view)

// ---------------- device scratch (static allocation; no cudaMalloc) -------------
__device__ __align__(16) __half g_hh0[(size_t)NDIM * BDIM];  // h ping  (N,B) fp16
__device__ __align__(16) __half g_hh1[(size_t)NDIM * BDIM];  // h pong  (N,B) fp16
__device__ __align__(16) float  g_c [(size_t)NDIM * BDIM];   // cell state fp32; iter4 reuses as fp32 h-out

__device__ int                g_colcnt[NDIM];
__device__ int                g_colstart[NDIM + 1];
__device__ int                g_cur[NDIM];
__device__ unsigned long long g_pack[NNZ];      // [62:46]=eid [45:32]=row [31:0]=val bits
__device__ int                g_idx_nonzero_odd = 0;   // monotonic 0->1; pure fn of input

// ---------------- init: zero counters + index-dtype detection (fused) ------------
__global__ void k_init(const int* __restrict__ w) {
    int i = blockIdx.x * blockDim.x + threadIdx.x;
    if (i < NDIM) g_colcnt[i] = 0;
    if (i < NNZ && w[2 * i + 1] != 0) atomicOr(&g_idx_nonzero_odd, 1);
}

__device__ __forceinline__ void load_rc(const void* idx, int e, int& row, int& col) {
    if (g_idx_nonzero_odd) {               // int32 pairs
        const int* p = (const int*)idx;
        row = p[2 * e + 0];
        col = p[2 * e + 1];
    } else {                               // int64 pairs
        const long long* p = (const long long*)idx;
        row = (int)p[2 * e + 0];
        col = (int)p[2 * e + 1];
    }
    row &= (NDIM - 1);
    col &= (NDIM - 1);
}

__global__ void k_hist(const void* __restrict__ idx) {
    int e = blockIdx.x * blockDim.x + threadIdx.x;
    if (e < NNZ) {
        int row, col;
        load_rc(idx, e, row, col);
        atomicAdd(&g_colcnt[col], 1);
    }
}

// 1024 threads, 1 block: int4 loads, shfl warp scan + block scan over warp sums
__global__ void __launch_bounds__(1024) k_scan() {
    __shared__ int ws[32];
    int t = threadIdx.x;                 // 0..1023, owns 16 consecutive bins
    const int4* cc = (const int4*)g_colcnt;
    int4 a0 = cc[t * 4 + 0], a1 = cc[t * 4 + 1], a2 = cc[t * 4 + 2], a3 = cc[t * 4 + 3];
    int v[16] = {a0.x, a0.y, a0.z, a0.w, a1.x, a1.y, a1.z, a1.w,
                 a2.x, a2.y, a2.z, a2.w, a3.x, a3.y, a3.z, a3.w};
    int tot = 0;
    #pragma unroll
    for (int k = 0; k < 16; k++) tot += v[k];

    int lane = t & 31, w = t >> 5;
    int sc = tot;
    #pragma unroll
    for (int off = 1; off < 32; off <<= 1) {
        int n = __shfl_up_sync(0xffffffffu, sc, off);
        if (lane >= off) sc += n;
    }
    if (lane == 31) ws[w] = sc;
    __syncthreads();
    if (w == 0) {
        int x = ws[lane];
        #pragma unroll
        for (int off = 1; off < 32; off <<= 1) {
            int n = __shfl_up_sync(0xffffffffu, x, off);
            if (lane >= off) x += n;
        }
        ws[lane] = x;
    }
    __syncthreads();
    int base = (w ? ws[w - 1] : 0) + (sc - tot);
    #pragma unroll
    for (int k = 0; k < 16; k++) {
        g_colstart[t * 16 + k] = base;
        g_cur[t * 16 + k] = base;
        base += v[k];
    }
    if (t == 1023) g_colstart[NDIM] = base;   // == NNZ
}

__global__ void k_scatter(const void* __restrict__ idx,
                          const float* __restrict__ vals) {
    int e = blockIdx.x * blockDim.x + threadIdx.x;
    if (e < NNZ) {
        int row, col;
        load_rc(idx, e, row, col);
        int pos = atomicAdd(&g_cur[col], 1);
        unsigned long long p = ((unsigned long long)e << 46)
                             | ((unsigned long long)(unsigned)row << 32)
                             | (unsigned)__float_as_int(vals[e]);
        g_pack[pos] = p;
    }
}

// deterministic order: sort each segment by packed key (eid in top bits)
__global__ void k_segsort() {
    int col = blockIdx.x * blockDim.x + threadIdx.x;
    if (col >= NDIM) return;
    int s = g_colstart[col], e = g_colstart[col + 1], n = e - s;
    if (n <= 1) return;
    if (n <= 32) {
        unsigned long long buf[32];
        for (int k = 0; k < n; k++) buf[k] = g_pack[s + k];
        for (int a = 1; a < n; a++) {
            unsigned long long key = buf[a];
            int b = a - 1;
            while (b >= 0 && buf[b] > key) { buf[b + 1] = buf[b]; b--; }
            buf[b + 1] = key;
        }
        for (int k = 0; k < n; k++) g_pack[s + k] = buf[k];
    } else {
        for (int a = s + 1; a < e; a++) {
            unsigned long long key = g_pack[a];
            int b = a - 1;
            while (b >= s && g_pack[b] > key) { g_pack[b + 1] = g_pack[b]; b--; }
            g_pack[b + 1] = key;
        }
    }
}

// ---------------- transpose in: x (B,N) fp32 -> g_hh0 (N,B) fp16 -----------------
__global__ void k_transpose_in(const float* __restrict__ x) {
    __shared__ float tile[32][33];
    int nBase = blockIdx.x * 32;
    int bBase = blockIdx.y * 32;
    int tx = threadIdx.x, ty = threadIdx.y;
    #pragma unroll
    for (int i = ty; i < 32; i += 8)
        tile[i][tx] = x[(size_t)(bBase + i) * NDIM + nBase + tx];
    __syncthreads();
    #pragma unroll
    for (int i = ty; i < 32; i += 8)
        g_hh0[(size_t)(nBase + i) * BDIM + bBase + tx] = __float2half(tile[tx][i]);
}

// ---------------- fused SpMM + LSTM gate iteration ------------------------------
__device__ __forceinline__ float lstm_elem(float z, float& c,
                                           float ebi, float ebf, float ebo, float ebg2) {
    float ez = __expf(-z);
    float i = __fdividef(1.0f, 1.0f + ez * ebi);
    float f = __fdividef(1.0f, 1.0f + ez * ebf);
    float o = __fdividef(1.0f, 1.0f + ez * ebo);
    float w = ez * ez * ebg2;                         // e^{-2(z+b_g)}
    float g = __fdividef(2.0f, 1.0f + w) - 1.0f;      // tanh(z+b_g)
    c = f * c + i * g;
    float ec = __expf(-2.0f * c);
    float th = __fdividef(1.0f - ec, 1.0f + ec);      // tanh(c)
    return o * th;
}

// flip==0: read g_hh0 write g_hh1; flip==1: read g_hh1 write g_hh0.
// first: c starts at 0 (skip load). last: skip c store, write h fp32 into g_c.
__global__ void __launch_bounds__(128)
k_iter(int flip, int first, int last,
       const float* __restrict__ bi_, const float* __restrict__ bf_,
       const float* __restrict__ bo_, const float* __restrict__ bg_) {
    const uint2* hp = (const uint2*)(flip ? g_hh1 : g_hh0);   // 4 halves per elem
    uint2*       hd = (uint2*)(flip ? g_hh0 : g_hh1);

    int col = blockIdx.x;
    int t   = threadIdx.x;                 // 0..127, owns 4 batch elems
    int s = g_colstart[col], e = g_colstart[col + 1];

    float4 acc = make_float4(0.f, 0.f, 0.f, 0.f);
    int j = s;
    unsigned long long pf = (j < e) ? g_pack[j] : 0ull;
    while (j < e) {
        unsigned long long p = pf;
        if (j + 1 < e) pf = g_pack[j + 1];
        int   r = (int)((p >> 32) & 0x3FFFu);
        float v = __int_as_float((int)(unsigned)p);
        uint2 hraw = hp[(size_t)r * BH4 + t];
        float2 h01 = __half22float2(*(const __half2*)&hraw.x);
        float2 h23 = __half22float2(*(const __half2*)&hraw.y);
        acc.x = fmaf(v, h01.x, acc.x);
        acc.y = fmaf(v, h01.y, acc.y);
        acc.z = fmaf(v, h23.x, acc.z);
        acc.w = fmaf(v, h23.y, acc.w);
        j++;
    }

    float ebi  = __expf(-bi_[col]);
    float ebf  = __expf(-bf_[col]);
    float ebo  = __expf(-bo_[col]);
    float ebg2 = __expf(-2.0f * bg_[col]);

    size_t co = (size_t)col * B4 + t;
    float4* cp = (float4*)g_c;
    float4  cv = first ? make_float4(0.f, 0.f, 0.f, 0.f) : cp[co];

    float4 hout;
    hout.x = lstm_elem(acc.x, cv.x, ebi, ebf, ebo, ebg2);
    hout.y = lstm_elem(acc.y, cv.y, ebi, ebf, ebo, ebg2);
    hout.z = lstm_elem(acc.z, cv.z, ebi, ebf, ebo, ebg2);
    hout.w = lstm_elem(acc.w, cv.w, ebi, ebf, ebo, ebg2);

    if (last) {
        // final h in fp32 -> reuse g_c (c no longer needed); output stays fp32-exact
        cp[co] = hout;
    } else {
        cp[co] = cv;
        uint2 hw;
        *(__half2*)&hw.x = __floats2half2_rn(hout.x, hout.y);
        *(__half2*)&hw.y = __floats2half2_rn(hout.z, hout.w);
        hd[co] = hw;
    }
}

// ---------------- transpose out: g_c (N,B) fp32 -> out (B,N) ---------------------
__global__ void k_transpose_out(float* __restrict__ out) {
    __shared__ float tile[32][33];
    int nBase = blockIdx.x * 32;
    int bBase = blockIdx.y * 32;
    int tx = threadIdx.x, ty = threadIdx.y;
    #pragma unroll
    for (int i = ty; i < 32; i += 8)
        tile[i][tx] = g_c[(size_t)(nBase + i) * BDIM + bBase + tx];
    __syncthreads();
    #pragma unroll
    for (int i = ty; i < 32; i += 8)
        out[(size_t)(bBase + i) * NDIM + nBase + tx] = tile[tx][i];
}

// ---------------- launch ---------------------------------------------------------
extern "C" void kernel_launch(void* const* d_in, const int* in_sizes, int n_in,
                              void* d_out, int out_size) {
    const float* x    = nullptr;
    const float* vals = nullptr;
    const float* bias[4] = {nullptr, nullptr, nullptr, nullptr};
    const void*  idx  = nullptr;
    int nbias = 0;
    for (int i = 0; i < n_in; i++) {
        int sz = in_sizes[i];
        if (sz == NDIM * BDIM)       x = (const float*)d_in[i];
        else if (sz == NNZ)          vals = (const float*)d_in[i];
        else if (sz == NDIM)         { if (nbias < 4) bias[nbias++] = (const float*)d_in[i]; }
        else                         idx = d_in[i];
    }
    const float* b_i = bias[0];
    const float* b_f = bias[1];
    const float* b_o = bias[2];
    const float* b_g = bias[3];
    float* out = (float*)d_out;
    (void)out_size;

    // build CSC (deterministic via per-segment sort on packed entry id)
    k_init   <<<(NNZ + 255) / 256, 256>>>((const int*)idx);
    k_hist   <<<(NNZ + 255) / 256, 256>>>(idx);
    k_scan   <<<1, 1024>>>();
    k_scatter<<<(NNZ + 255) / 256, 256>>>(idx, vals);
    k_segsort<<<(NDIM + 255) / 256, 256>>>();

    // state init: h = half(x^T); c handled by `first` flag
    dim3 tb(32, 8);
    dim3 tg(NDIM / 32, BDIM / 32);
    k_transpose_in<<<tg, tb>>>(x);

    // 4 fused iterations; h ping-pong hh0->hh1->hh0->hh1; last writes fp32 into g_c
    k_iter<<<NDIM, 128>>>(0, 1, 0, b_i, b_f, b_o, b_g);
    k_iter<<<NDIM, 128>>>(1, 0, 0, b_i, b_f, b_o, b_g);
    k_iter<<<NDIM, 128>>>(0, 0, 0, b_i, b_f, b_o, b_g);
    k_iter<<<NDIM, 128>>>(1, 0, 1, b_i, b_f, b_o, b_g);

    // out (B,N) = transpose(g_c)
    k_transpose_out<<<tg, tb>>>(out);
}

// round 9
// speedup vs baseline: 1.3848x; 1.0979x over previous
#include <cuda_runtime.h>
#include <cuda_fp16.h>
#include <cstdint>

#define NDIM 16384
#define BDIM 512
#define NNZ  131072
#define B4   (BDIM/4)   // 128 float4 / uint2 per column

// ---------------- device scratch (static allocation; no cudaMalloc) -------------
__device__ __align__(16) __half g_hh0[(size_t)NDIM * BDIM];   // h ping (N,B) fp16
__device__ __align__(16) __half g_hh1[(size_t)NDIM * BDIM];   // h pong (N,B) fp16
__device__ __align__(16) __half g_ch [(size_t)NDIM * BDIM];   // cell state fp16
__device__ __align__(16) float  g_hfinal[(size_t)NDIM * BDIM];// final h fp32 (N,B)

__device__ int                g_colcnt[NDIM];
__device__ int                g_colstart[NDIM + 1];
__device__ int                g_cur[NDIM];
__device__ unsigned long long g_pack[NNZ];      // [45:32]=row [31:0]=val bits
__device__ int                g_idx_nonzero_odd = 0;   // monotonic 0->1; pure fn of input

// ---------------- init: zero counters + index-dtype detection (fused) ------------
__global__ void k_init(const int* __restrict__ w) {
    int i = blockIdx.x * blockDim.x + threadIdx.x;
    if (i < NDIM) g_colcnt[i] = 0;
    if (i < NNZ && w[2 * i + 1] != 0) atomicOr(&g_idx_nonzero_odd, 1);
}

__device__ __forceinline__ void load_rc(const void* idx, int e, int& row, int& col) {
    if (g_idx_nonzero_odd) {               // int32 pairs
        const int* p = (const int*)idx;
        row = p[2 * e + 0];
        col = p[2 * e + 1];
    } else {                               // int64 pairs
        const long long* p = (const long long*)idx;
        row = (int)p[2 * e + 0];
        col = (int)p[2 * e + 1];
    }
    row &= (NDIM - 1);
    col &= (NDIM - 1);
}

__global__ void k_hist(const void* __restrict__ idx) {
    int e = blockIdx.x * blockDim.x + threadIdx.x;
    if (e < NNZ) {
        int row, col;
        load_rc(idx, e, row, col);
        atomicAdd(&g_colcnt[col], 1);
    }
}

// 1024 threads, 1 block: int4 loads, shfl warp scan + block scan over warp sums
__global__ void __launch_bounds__(1024) k_scan() {
    __shared__ int ws[32];
    int t = threadIdx.x;                 // 0..1023, owns 16 consecutive bins
    const int4* cc = (const int4*)g_colcnt;
    int4 a0 = cc[t * 4 + 0], a1 = cc[t * 4 + 1], a2 = cc[t * 4 + 2], a3 = cc[t * 4 + 3];
    int v[16] = {a0.x, a0.y, a0.z, a0.w, a1.x, a1.y, a1.z, a1.w,
                 a2.x, a2.y, a2.z, a2.w, a3.x, a3.y, a3.z, a3.w};
    int tot = 0;
    #pragma unroll
    for (int k = 0; k < 16; k++) tot += v[k];

    int lane = t & 31, w = t >> 5;
    int sc = tot;
    #pragma unroll
    for (int off = 1; off < 32; off <<= 1) {
        int n = __shfl_up_sync(0xffffffffu, sc, off);
        if (lane >= off) sc += n;
    }
    if (lane == 31) ws[w] = sc;
    __syncthreads();
    if (w == 0) {
        int x = ws[lane];
        #pragma unroll
        for (int off = 1; off < 32; off <<= 1) {
            int n = __shfl_up_sync(0xffffffffu, x, off);
            if (lane >= off) x += n;
        }
        ws[lane] = x;
    }
    __syncthreads();
    int base = (w ? ws[w - 1] : 0) + (sc - tot);
    #pragma unroll
    for (int k = 0; k < 16; k++) {
        g_colstart[t * 16 + k] = base;
        g_cur[t * 16 + k] = base;
        base += v[k];
    }
    if (t == 1023) g_colstart[NDIM] = base;   // == NNZ
}

__global__ void k_scatter(const void* __restrict__ idx,
                          const float* __restrict__ vals) {
    int e = blockIdx.x * blockDim.x + threadIdx.x;
    if (e < NNZ) {
        int row, col;
        load_rc(idx, e, row, col);
        int pos = atomicAdd(&g_cur[col], 1);
        unsigned long long p = ((unsigned long long)(unsigned)row << 32)
                             | (unsigned)__float_as_int(vals[e]);
        g_pack[pos] = p;
    }
}

// ---------------- transpose in: x (B,N) fp32 -> g_hh0 (N,B) fp16 -----------------
__global__ void k_transpose_in(const float* __restrict__ x) {
    __shared__ float tile[32][33];
    int nBase = blockIdx.x * 32;
    int bBase = blockIdx.y * 32;
    int tx = threadIdx.x, ty = threadIdx.y;
    #pragma unroll
    for (int i = ty; i < 32; i += 8)
        tile[i][tx] = x[(size_t)(bBase + i) * NDIM + nBase + tx];
    __syncthreads();
    #pragma unroll
    for (int i = ty; i < 32; i += 8)
        g_hh0[(size_t)(nBase + i) * BDIM + bBase + tx] = __float2half(tile[tx][i]);
}

// ---------------- fused SpMM + LSTM gate iteration ------------------------------
__device__ __forceinline__ float lstm_elem(float z, float& c,
                                           float ebi, float ebf, float ebo, float ebg2) {
    float ez = __expf(-z);
    float i = __fdividef(1.0f, 1.0f + ez * ebi);
    float f = __fdividef(1.0f, 1.0f + ez * ebf);
    float o = __fdividef(1.0f, 1.0f + ez * ebo);
    float w = ez * ez * ebg2;                         // e^{-2(z+b_g)}
    float g = __fdividef(2.0f, 1.0f + w) - 1.0f;      // tanh(z+b_g)
    c = f * c + i * g;
    float ec = __expf(-2.0f * c);
    float th = __fdividef(1.0f - ec, 1.0f + ec);      // tanh(c)
    return o * th;
}

__device__ __forceinline__ void gather_fma(const uint2* __restrict__ hp,
                                           unsigned long long p, int t, float4& acc) {
    int   r = (int)((p >> 32) & 0x3FFFu);
    float v = __int_as_float((int)(unsigned)p);
    uint2 hraw = hp[(size_t)r * B4 + t];
    float2 h01 = __half22float2(*(const __half2*)&hraw.x);
    float2 h23 = __half22float2(*(const __half2*)&hraw.y);
    acc.x = fmaf(v, h01.x, acc.x);
    acc.y = fmaf(v, h01.y, acc.y);
    acc.z = fmaf(v, h23.x, acc.z);
    acc.w = fmaf(v, h23.y, acc.w);
}

// flip==0: read g_hh0 write g_hh1; flip==1: read g_hh1 write g_hh0.
// first: c starts at 0 (skip load). last: skip c store, write h fp32 into g_hfinal.
__global__ void __launch_bounds__(128)
k_iter(int flip, int first, int last,
       const float* __restrict__ bi_, const float* __restrict__ bf_,
       const float* __restrict__ bo_, const float* __restrict__ bg_) {
    const uint2* hp = (const uint2*)(flip ? g_hh1 : g_hh0);
    uint2*       hd = (uint2*)(flip ? g_hh0 : g_hh1);

    int col = blockIdx.x;
    int t   = threadIdx.x;                 // 0..127, owns 4 batch elems
    int s = g_colstart[col], e = g_colstart[col + 1];

    float4 acc = make_float4(0.f, 0.f, 0.f, 0.f);
    int j = s;
    // 4-deep pipelined main loop: issue 4 pack loads + 4 gathers before the FMAs
    for (; j + 4 <= e; j += 4) {
        unsigned long long p0 = g_pack[j + 0];
        unsigned long long p1 = g_pack[j + 1];
        unsigned long long p2 = g_pack[j + 2];
        unsigned long long p3 = g_pack[j + 3];
        int r0 = (int)((p0 >> 32) & 0x3FFFu);
        int r1 = (int)((p1 >> 32) & 0x3FFFu);
        int r2 = (int)((p2 >> 32) & 0x3FFFu);
        int r3 = (int)((p3 >> 32) & 0x3FFFu);
        uint2 h0 = hp[(size_t)r0 * B4 + t];
        uint2 h1 = hp[(size_t)r1 * B4 + t];
        uint2 h2 = hp[(size_t)r2 * B4 + t];
        uint2 h3 = hp[(size_t)r3 * B4 + t];
        float v0 = __int_as_float((int)(unsigned)p0);
        float v1 = __int_as_float((int)(unsigned)p1);
        float v2 = __int_as_float((int)(unsigned)p2);
        float v3 = __int_as_float((int)(unsigned)p3);
        float2 a01, a23;
        a01 = __half22float2(*(const __half2*)&h0.x); a23 = __half22float2(*(const __half2*)&h0.y);
        acc.x = fmaf(v0, a01.x, acc.x); acc.y = fmaf(v0, a01.y, acc.y);
        acc.z = fmaf(v0, a23.x, acc.z); acc.w = fmaf(v0, a23.y, acc.w);
        a01 = __half22float2(*(const __half2*)&h1.x); a23 = __half22float2(*(const __half2*)&h1.y);
        acc.x = fmaf(v1, a01.x, acc.x); acc.y = fmaf(v1, a01.y, acc.y);
        acc.z = fmaf(v1, a23.x, acc.z); acc.w = fmaf(v1, a23.y, acc.w);
        a01 = __half22float2(*(const __half2*)&h2.x); a23 = __half22float2(*(const __half2*)&h2.y);
        acc.x = fmaf(v2, a01.x, acc.x); acc.y = fmaf(v2, a01.y, acc.y);
        acc.z = fmaf(v2, a23.x, acc.z); acc.w = fmaf(v2, a23.y, acc.w);
        a01 = __half22float2(*(const __half2*)&h3.x); a23 = __half22float2(*(const __half2*)&h3.y);
        acc.x = fmaf(v3, a01.x, acc.x); acc.y = fmaf(v3, a01.y, acc.y);
        acc.z = fmaf(v3, a23.x, acc.z); acc.w = fmaf(v3, a23.y, acc.w);
    }
    for (; j < e; j++) gather_fma(hp, g_pack[j], t, acc);

    float ebi  = __expf(-bi_[col]);
    float ebf  = __expf(-bf_[col]);
    float ebo  = __expf(-bo_[col]);
    float ebg2 = __expf(-2.0f * bg_[col]);

    size_t co = (size_t)col * B4 + t;
    uint2* chp = (uint2*)g_ch;             // 4 halves of c per thread
    float4 cv;
    if (first) {
        cv = make_float4(0.f, 0.f, 0.f, 0.f);
    } else {
        uint2 craw = chp[co];
        float2 c01 = __half22float2(*(const __half2*)&craw.x);
        float2 c23 = __half22float2(*(const __half2*)&craw.y);
        cv = make_float4(c01.x, c01.y, c23.x, c23.y);
    }

    float4 hout;
    hout.x = lstm_elem(acc.x, cv.x, ebi, ebf, ebo, ebg2);
    hout.y = lstm_elem(acc.y, cv.y, ebi, ebf, ebo, ebg2);
    hout.z = lstm_elem(acc.z, cv.z, ebi, ebf, ebo, ebg2);
    hout.w = lstm_elem(acc.w, cv.w, ebi, ebf, ebo, ebg2);

    if (last) {
        ((float4*)g_hfinal)[co] = hout;    // fp32-exact final h
    } else {
        uint2 cw;
        *(__half2*)&cw.x = __floats2half2_rn(cv.x, cv.y);
        *(__half2*)&cw.y = __floats2half2_rn(cv.z, cv.w);
        chp[co] = cw;
        uint2 hw;
        *(__half2*)&hw.x = __floats2half2_rn(hout.x, hout.y);
        *(__half2*)&hw.y = __floats2half2_rn(hout.z, hout.w);
        hd[co] = hw;
    }
}

// ---------------- transpose out: g_hfinal (N,B) fp32 -> out (B,N) ----------------
__global__ void k_transpose_out(float* __restrict__ out) {
    __shared__ float tile[32][33];
    int nBase = blockIdx.x * 32;
    int bBase = blockIdx.y * 32;
    int tx = threadIdx.x, ty = threadIdx.y;
    #pragma unroll
    for (int i = ty; i < 32; i += 8)
        tile[i][tx] = g_hfinal[(size_t)(nBase + i) * BDIM + bBase + tx];
    __syncthreads();
    #pragma unroll
    for (int i = ty; i < 32; i += 8)
        out[(size_t)(bBase + i) * NDIM + nBase + tx] = tile[tx][i];
}

// ---------------- launch ---------------------------------------------------------
extern "C" void kernel_launch(void* const* d_in, const int* in_sizes, int n_in,
                              void* d_out, int out_size) {
    const float* x    = nullptr;
    const float* vals = nullptr;
    const float* bias[4] = {nullptr, nullptr, nullptr, nullptr};
    const void*  idx  = nullptr;
    int nbias = 0;
    for (int i = 0; i < n_in; i++) {
        int sz = in_sizes[i];
        if (sz == NDIM * BDIM)       x = (const float*)d_in[i];
        else if (sz == NNZ)          vals = (const float*)d_in[i];
        else if (sz == NDIM)         { if (nbias < 4) bias[nbias++] = (const float*)d_in[i]; }
        else                         idx = d_in[i];
    }
    const float* b_i = bias[0];
    const float* b_f = bias[1];
    const float* b_o = bias[2];
    const float* b_g = bias[3];
    float* out = (float*)d_out;
    (void)out_size;

    // build CSC
    k_init   <<<(NNZ + 255) / 256, 256>>>((const int*)idx);
    k_hist   <<<(NNZ + 255) / 256, 256>>>(idx);
    k_scan   <<<1, 1024>>>();
    k_scatter<<<(NNZ + 255) / 256, 256>>>(idx, vals);

    // state init: h = half(x^T); c handled by `first` flag
    dim3 tb(32, 8);
    dim3 tg(NDIM / 32, BDIM / 32);
    k_transpose_in<<<tg, tb>>>(x);

    // 4 fused iterations; h ping-pong; last writes fp32 into g_hfinal
    k_iter<<<NDIM, 128>>>(0, 1, 0, b_i, b_f, b_o, b_g);
    k_iter<<<NDIM, 128>>>(1, 0, 0, b_i, b_f, b_o, b_g);
    k_iter<<<NDIM, 128>>>(0, 0, 0, b_i, b_f, b_o, b_g);
    k_iter<<<NDIM, 128>>>(1, 0, 1, b_i, b_f, b_o, b_g);

    // out (B,N) = transpose(g_hfinal)
    k_transpose_out<<<tg, tb>>>(out);
}